// round 1
// baseline (speedup 1.0000x reference)
#include <cuda_runtime.h>
#include <math.h>
#include <stdint.h>

#define ND   64
#define ED   32
#define CIN  160      // 2*ND + ED
#define HID  256
#define MSGD 128
#define MAX_EDGES 800000
#define MAX_NODES 50000

#define BM    64
#define INPAD 164     // 160 padded: stride%32 == 4 -> conflict-free
#define HPAD  260     // 256 padded
#define XPAD  132     // 128 padded

// ---- scratch (device globals; no runtime allocation allowed) ----
__device__ int   g_count;
__device__ int   g_active[MAX_EDGES];
__device__ int   g_crecv[MAX_EDGES];
__device__ float g_msg[(size_t)MAX_EDGES * MSGD];
__device__ float g_logits[MAX_EDGES];
__device__ float g_e[MAX_EDGES];
__device__ float g_segmax[MAX_NODES];
__device__ float g_denom[MAX_NODES];
__device__ float g_aggr[(size_t)MAX_NODES * MSGD];

// ---------------- init: zero aggr/denom, segmax=-inf, count=0 ----------------
__global__ void init_kernel(int n_agents) {
    int i = blockIdx.x * blockDim.x + threadIdx.x;
    int total = n_agents * MSGD;
    if (i < total) g_aggr[i] = 0.f;
    if (i < n_agents) { g_segmax[i] = -INFINITY; g_denom[i] = 0.f; }
    if (i == 0) g_count = 0;
}

// ---------------- compact: keep only edges whose receiver is an agent --------
__global__ void compact_kernel(const int* __restrict__ recv, int n_edges, int n_agents) {
    int i = blockIdx.x * blockDim.x + threadIdx.x;
    if (i >= n_edges) return;
    int r = recv[i];
    if (r < n_agents) {
        int p = atomicAdd(&g_count, 1);
        g_active[p] = i;
        g_crecv[p]  = r;
    }
}

// ---------------- fused edge MLP: msg + gate logits --------------------------
// block = 256 threads, tile = 64 edges. smem: in[64][164] + h[64][260]
__global__ __launch_bounds__(256, 2) void edge_mlp_kernel(
    const float* __restrict__ node_feats, const float* __restrict__ edge_feats,
    const float* __restrict__ W1, const float* __restrict__ b1,
    const float* __restrict__ W2, const float* __restrict__ b2,
    const float* __restrict__ w_gate, const float* __restrict__ b_gate,
    const int* __restrict__ senders, const int* __restrict__ receivers)
{
    extern __shared__ float smem[];
    float (*s_in)[INPAD] = (float (*)[INPAD])smem;
    float (*s_h)[HPAD]   = (float (*)[HPAD])(smem + BM * INPAD);

    const int cnt = g_count;
    const int e0  = blockIdx.x * BM;
    if (e0 >= cnt) return;
    const int tid = threadIdx.x;

    // gather [sender(16 f4) | receiver(16 f4) | edge(8 f4)] per edge
    for (int idx = tid; idx < BM * 40; idx += 256) {
        int m = idx / 40, p = idx - m * 40;
        int ci = e0 + m;
        float4 v = make_float4(0.f, 0.f, 0.f, 0.f);
        if (ci < cnt) {
            int e = g_active[ci];
            if (p < 16)      v = ((const float4*)(node_feats + (size_t)senders[e] * ND))[p];
            else if (p < 32) v = ((const float4*)(node_feats + (size_t)receivers[e] * ND))[p - 16];
            else             v = ((const float4*)(edge_feats + (size_t)e * ED))[p - 32];
        }
        *(float4*)&s_in[m][p * 4] = v;
    }
    __syncthreads();

    const int tx = tid & 15, ty = tid >> 4;
    const int n0 = tx * 16, m0 = ty * 4;

    // ---- GEMM1: [64x160] @ [160x256], per-thread 4x16 ----
    float acc[4][16];
    {
        float bv[16];
        *(float4*)&bv[0]  = *(const float4*)(b1 + n0);
        *(float4*)&bv[4]  = *(const float4*)(b1 + n0 + 4);
        *(float4*)&bv[8]  = *(const float4*)(b1 + n0 + 8);
        *(float4*)&bv[12] = *(const float4*)(b1 + n0 + 12);
        #pragma unroll
        for (int i = 0; i < 4; i++)
            #pragma unroll
            for (int j = 0; j < 16; j++) acc[i][j] = bv[j];
    }
    #pragma unroll 2
    for (int k = 0; k < CIN; k++) {
        float a0 = s_in[m0 + 0][k], a1 = s_in[m0 + 1][k];
        float a2 = s_in[m0 + 2][k], a3 = s_in[m0 + 3][k];
        const float* wr = W1 + k * HID + n0;
        float4 w0 = *(const float4*)(wr);
        float4 w1 = *(const float4*)(wr + 4);
        float4 w2 = *(const float4*)(wr + 8);
        float4 w3 = *(const float4*)(wr + 12);
        float w[16] = {w0.x,w0.y,w0.z,w0.w, w1.x,w1.y,w1.z,w1.w,
                       w2.x,w2.y,w2.z,w2.w, w3.x,w3.y,w3.z,w3.w};
        #pragma unroll
        for (int j = 0; j < 16; j++) {
            acc[0][j] = fmaf(a0, w[j], acc[0][j]);
            acc[1][j] = fmaf(a1, w[j], acc[1][j]);
            acc[2][j] = fmaf(a2, w[j], acc[2][j]);
            acc[3][j] = fmaf(a3, w[j], acc[3][j]);
        }
    }
    // relu -> smem
    #pragma unroll
    for (int i = 0; i < 4; i++) {
        #pragma unroll
        for (int g = 0; g < 4; g++) {
            float4 r;
            r.x = fmaxf(acc[i][g*4+0], 0.f); r.y = fmaxf(acc[i][g*4+1], 0.f);
            r.z = fmaxf(acc[i][g*4+2], 0.f); r.w = fmaxf(acc[i][g*4+3], 0.f);
            *(float4*)&s_h[m0 + i][n0 + g * 4] = r;
        }
    }
    __syncthreads();

    // ---- GEMM2: [64x256] @ [256x128], per-thread 4x8 ----
    const int c0 = tx * 8;
    float acc2[4][8];
    {
        float bv[8];
        *(float4*)&bv[0] = *(const float4*)(b2 + c0);
        *(float4*)&bv[4] = *(const float4*)(b2 + c0 + 4);
        #pragma unroll
        for (int i = 0; i < 4; i++)
            #pragma unroll
            for (int j = 0; j < 8; j++) acc2[i][j] = bv[j];
    }
    #pragma unroll 2
    for (int k = 0; k < HID; k++) {
        float a0 = s_h[m0 + 0][k], a1 = s_h[m0 + 1][k];
        float a2 = s_h[m0 + 2][k], a3 = s_h[m0 + 3][k];
        const float* wr = W2 + k * MSGD + c0;
        float4 w0 = *(const float4*)(wr);
        float4 w1 = *(const float4*)(wr + 4);
        float w[8] = {w0.x,w0.y,w0.z,w0.w, w1.x,w1.y,w1.z,w1.w};
        #pragma unroll
        for (int j = 0; j < 8; j++) {
            acc2[0][j] = fmaf(a0, w[j], acc2[0][j]);
            acc2[1][j] = fmaf(a1, w[j], acc2[1][j]);
            acc2[2][j] = fmaf(a2, w[j], acc2[2][j]);
            acc2[3][j] = fmaf(a3, w[j], acc2[3][j]);
        }
    }

    // relu + gate partials + store msg
    float wg[8];
    *(float4*)&wg[0] = *(const float4*)(w_gate + c0);
    *(float4*)&wg[4] = *(const float4*)(w_gate + c0 + 4);
    float partial[4];
    #pragma unroll
    for (int i = 0; i < 4; i++) {
        float p = 0.f;
        #pragma unroll
        for (int j = 0; j < 8; j++) {
            float v = fmaxf(acc2[i][j], 0.f);
            acc2[i][j] = v;
            p = fmaf(v, wg[j], p);
        }
        partial[i] = p;
        int ci = e0 + m0 + i;
        if (ci < cnt) {
            float* dst = g_msg + (size_t)ci * MSGD + c0;
            *(float4*)(dst)     = make_float4(acc2[i][0], acc2[i][1], acc2[i][2], acc2[i][3]);
            *(float4*)(dst + 4) = make_float4(acc2[i][4], acc2[i][5], acc2[i][6], acc2[i][7]);
        }
    }
    // butterfly reduce across the 16-lane tx group
    #pragma unroll
    for (int o = 8; o >= 1; o >>= 1) {
        #pragma unroll
        for (int i = 0; i < 4; i++)
            partial[i] += __shfl_xor_sync(0xffffffffu, partial[i], o);
    }
    if (tx == 0) {
        float bg = b_gate[0];
        #pragma unroll
        for (int i = 0; i < 4; i++) {
            int ci = e0 + m0 + i;
            if (ci < cnt) g_logits[ci] = partial[i] + bg;
        }
    }
}

// ---------------- segment max (exact, sign-split int atomics) ----------------
__global__ void seg_max_kernel() {
    int i = blockIdx.x * blockDim.x + threadIdx.x;
    if (i >= g_count) return;
    float v = g_logits[i];
    int r = g_crecv[i];
    if (v >= 0.f) atomicMax((int*)(g_segmax + r), __float_as_int(v));
    else          atomicMin((unsigned int*)(g_segmax + r), (unsigned int)__float_as_int(v));
}

// ---------------- exp + segment denom ----------------------------------------
__global__ void exp_denom_kernel() {
    int i = blockIdx.x * blockDim.x + threadIdx.x;
    if (i >= g_count) return;
    int r = g_crecv[i];
    float ev = expf(g_logits[i] - g_segmax[r]);
    g_e[i] = ev;
    atomicAdd(g_denom + r, ev);
}

// ---------------- weighted scatter-add: one warp per edge --------------------
__global__ void aggr_kernel() {
    int w = (blockIdx.x * blockDim.x + threadIdx.x) >> 5;
    if (w >= g_count) return;
    int lane = threadIdx.x & 31;
    int r = g_crecv[w];
    float coef = g_e[w] / (g_denom[r] + 1e-9f);
    float4 mv = *(const float4*)(g_msg + (size_t)w * MSGD + lane * 4);
    float* dst = g_aggr + (size_t)r * MSGD + lane * 4;
    atomicAdd(dst + 0, coef * mv.x);
    atomicAdd(dst + 1, coef * mv.y);
    atomicAdd(dst + 2, coef * mv.z);
    atomicAdd(dst + 3, coef * mv.w);
}

// ---------------- agent MLP: relu(x@Wh1) -> relu(@Wh2) -> tanh(@Wout) --------
__global__ __launch_bounds__(256, 2) void agent_mlp_kernel(
    const float* __restrict__ W_h1, const float* __restrict__ b_h1,
    const float* __restrict__ W_h2, const float* __restrict__ b_h2,
    const float* __restrict__ W_out, const float* __restrict__ b_out,
    float* __restrict__ out, int n_agents)
{
    extern __shared__ float smem[];
    float (*s_x)[XPAD] = (float (*)[XPAD])smem;
    float (*s_h)[HPAD] = (float (*)[HPAD])(smem + BM * XPAD);

    const int r0 = blockIdx.x * BM;
    const int tid = threadIdx.x;

    for (int idx = tid; idx < BM * 32; idx += 256) {
        int m = idx >> 5, p = idx & 31;
        int r = r0 + m;
        float4 v = make_float4(0.f, 0.f, 0.f, 0.f);
        if (r < n_agents) v = *(const float4*)(g_aggr + (size_t)r * MSGD + p * 4);
        *(float4*)&s_x[m][p * 4] = v;
    }
    __syncthreads();

    const int tx = tid & 15, ty = tid >> 4;
    const int n0 = tx * 16, m0 = ty * 4;

    // GEMM1: [64x128] @ [128x256]
    float acc[4][16];
    {
        float bv[16];
        *(float4*)&bv[0]  = *(const float4*)(b_h1 + n0);
        *(float4*)&bv[4]  = *(const float4*)(b_h1 + n0 + 4);
        *(float4*)&bv[8]  = *(const float4*)(b_h1 + n0 + 8);
        *(float4*)&bv[12] = *(const float4*)(b_h1 + n0 + 12);
        #pragma unroll
        for (int i = 0; i < 4; i++)
            #pragma unroll
            for (int j = 0; j < 16; j++) acc[i][j] = bv[j];
    }
    #pragma unroll 2
    for (int k = 0; k < MSGD; k++) {
        float a0 = s_x[m0 + 0][k], a1 = s_x[m0 + 1][k];
        float a2 = s_x[m0 + 2][k], a3 = s_x[m0 + 3][k];
        const float* wr = W_h1 + k * HID + n0;
        float4 w0 = *(const float4*)(wr);
        float4 w1 = *(const float4*)(wr + 4);
        float4 w2 = *(const float4*)(wr + 8);
        float4 w3 = *(const float4*)(wr + 12);
        float w[16] = {w0.x,w0.y,w0.z,w0.w, w1.x,w1.y,w1.z,w1.w,
                       w2.x,w2.y,w2.z,w2.w, w3.x,w3.y,w3.z,w3.w};
        #pragma unroll
        for (int j = 0; j < 16; j++) {
            acc[0][j] = fmaf(a0, w[j], acc[0][j]);
            acc[1][j] = fmaf(a1, w[j], acc[1][j]);
            acc[2][j] = fmaf(a2, w[j], acc[2][j]);
            acc[3][j] = fmaf(a3, w[j], acc[3][j]);
        }
    }
    #pragma unroll
    for (int i = 0; i < 4; i++) {
        #pragma unroll
        for (int g = 0; g < 4; g++) {
            float4 r;
            r.x = fmaxf(acc[i][g*4+0], 0.f); r.y = fmaxf(acc[i][g*4+1], 0.f);
            r.z = fmaxf(acc[i][g*4+2], 0.f); r.w = fmaxf(acc[i][g*4+3], 0.f);
            *(float4*)&s_h[m0 + i][n0 + g * 4] = r;
        }
    }
    __syncthreads();

    // GEMM2: [64x256] @ [256x256]
    {
        float bv[16];
        *(float4*)&bv[0]  = *(const float4*)(b_h2 + n0);
        *(float4*)&bv[4]  = *(const float4*)(b_h2 + n0 + 4);
        *(float4*)&bv[8]  = *(const float4*)(b_h2 + n0 + 8);
        *(float4*)&bv[12] = *(const float4*)(b_h2 + n0 + 12);
        #pragma unroll
        for (int i = 0; i < 4; i++)
            #pragma unroll
            for (int j = 0; j < 16; j++) acc[i][j] = bv[j];
    }
    #pragma unroll 2
    for (int k = 0; k < HID; k++) {
        float a0 = s_h[m0 + 0][k], a1 = s_h[m0 + 1][k];
        float a2 = s_h[m0 + 2][k], a3 = s_h[m0 + 3][k];
        const float* wr = W_h2 + k * HID + n0;
        float4 w0 = *(const float4*)(wr);
        float4 w1 = *(const float4*)(wr + 4);
        float4 w2 = *(const float4*)(wr + 8);
        float4 w3 = *(const float4*)(wr + 12);
        float w[16] = {w0.x,w0.y,w0.z,w0.w, w1.x,w1.y,w1.z,w1.w,
                       w2.x,w2.y,w2.z,w2.w, w3.x,w3.y,w3.z,w3.w};
        #pragma unroll
        for (int j = 0; j < 16; j++) {
            acc[0][j] = fmaf(a0, w[j], acc[0][j]);
            acc[1][j] = fmaf(a1, w[j], acc[1][j]);
            acc[2][j] = fmaf(a2, w[j], acc[2][j]);
            acc[3][j] = fmaf(a3, w[j], acc[3][j]);
        }
    }

    // output head: relu then dot with W_out chunk, butterfly reduce, tanh
    float wo[16];
    *(float4*)&wo[0]  = *(const float4*)(W_out + n0);
    *(float4*)&wo[4]  = *(const float4*)(W_out + n0 + 4);
    *(float4*)&wo[8]  = *(const float4*)(W_out + n0 + 8);
    *(float4*)&wo[12] = *(const float4*)(W_out + n0 + 12);
    float partial[4];
    #pragma unroll
    for (int i = 0; i < 4; i++) {
        float p = 0.f;
        #pragma unroll
        for (int j = 0; j < 16; j++)
            p = fmaf(fmaxf(acc[i][j], 0.f), wo[j], p);
        partial[i] = p;
    }
    #pragma unroll
    for (int o = 8; o >= 1; o >>= 1) {
        #pragma unroll
        for (int i = 0; i < 4; i++)
            partial[i] += __shfl_xor_sync(0xffffffffu, partial[i], o);
    }
    if (tx == 0) {
        float bo = b_out[0];
        #pragma unroll
        for (int i = 0; i < 4; i++) {
            int r = r0 + m0 + i;
            if (r < n_agents) out[r] = tanhf(partial[i] + bo);
        }
    }
}

// ---------------------------------------------------------------------------
extern "C" void kernel_launch(void* const* d_in, const int* in_sizes, int n_in,
                              void* d_out, int out_size) {
    const float* node_feats = (const float*)d_in[0];
    const float* edge_feats = (const float*)d_in[1];
    const float* W_msg1 = (const float*)d_in[2];
    const float* b_msg1 = (const float*)d_in[3];
    const float* W_msg2 = (const float*)d_in[4];
    const float* b_msg2 = (const float*)d_in[5];
    const float* w_gate = (const float*)d_in[6];
    const float* b_gate = (const float*)d_in[7];
    const float* W_h1   = (const float*)d_in[8];
    const float* b_h1   = (const float*)d_in[9];
    const float* W_h2   = (const float*)d_in[10];
    const float* b_h2   = (const float*)d_in[11];
    const float* W_out  = (const float*)d_in[12];
    const float* b_out  = (const float*)d_in[13];
    const int* senders   = (const int*)d_in[14];
    const int* receivers = (const int*)d_in[15];
    float* out = (float*)d_out;

    const int n_edges  = in_sizes[14];
    const int n_agents = out_size;   // output is (n_agents, 1) float32

    const int SMEM_EDGE  = (BM * INPAD + BM * HPAD) * (int)sizeof(float);  // 108544
    const int SMEM_AGENT = (BM * XPAD + BM * HPAD) * (int)sizeof(float);   // 100352
    cudaFuncSetAttribute(edge_mlp_kernel, cudaFuncAttributeMaxDynamicSharedMemorySize, SMEM_EDGE);
    cudaFuncSetAttribute(agent_mlp_kernel, cudaFuncAttributeMaxDynamicSharedMemorySize, SMEM_AGENT);

    // 1. init scratch
    {
        int total = n_agents * MSGD;
        init_kernel<<<(total + 255) / 256, 256>>>(n_agents);
    }
    // 2. compact edges with receiver < n_agents
    compact_kernel<<<(n_edges + 255) / 256, 256>>>(receivers, n_edges, n_agents);
    // 3. fused edge MLP over compacted edges (grid sized for worst case)
    {
        int grid = (n_edges + BM - 1) / BM;
        edge_mlp_kernel<<<grid, 256, SMEM_EDGE>>>(
            node_feats, edge_feats, W_msg1, b_msg1, W_msg2, b_msg2,
            w_gate, b_gate, senders, receivers);
    }
    // 4-5. segment softmax
    seg_max_kernel<<<(n_edges + 255) / 256, 256>>>();
    exp_denom_kernel<<<(n_edges + 255) / 256, 256>>>();
    // 6. weighted scatter-add (one warp per edge)
    {
        long long warps = n_edges;
        int grid = (int)((warps * 32 + 255) / 256);
        aggr_kernel<<<grid, 256>>>();
    }
    // 7. agent MLP
    agent_mlp_kernel<<<(n_agents + BM - 1) / BM, 256, SMEM_AGENT>>>(
        W_h1, b_h1, W_h2, b_h2, W_out, b_out, out, n_agents);
}